// round 11
// baseline (speedup 1.0000x reference)
#include <cuda_runtime.h>
#include <cstdint>

#define NN 1000000
#define NE 8000000
#define EMB 64
#define NBLK 977            // ceil(NN/1024)

// Scratch (no cudaMalloc allowed)
__device__ float g_h[(size_t)NN * EMB];   // projected features [NN,64]
__device__ int g_off[NN + 1];             // CSR row offsets (exclusive)
__device__ int g_cursor[NN];              // counts, then scatter cursors
__device__ int g_scol[NE];                // col indices sorted by row
__device__ int g_blocksums[NBLK];

__device__ __forceinline__ float leaky(float x) { return fmaxf(x, 0.01f * x); }

// ---- packed f32x2 helpers (sm_103a) ----
__device__ __forceinline__ unsigned long long pack2(float x, float y) {
    unsigned long long u;
    asm("mov.b64 %0, {%1, %2};" : "=l"(u) : "r"(__float_as_uint(x)), "r"(__float_as_uint(y)));
    return u;
}
__device__ __forceinline__ void unpack2(unsigned long long u, float& x, float& y) {
    unsigned lo, hi;
    asm("mov.b64 {%0, %1}, %2;" : "=r"(lo), "=r"(hi) : "l"(u));
    x = __uint_as_float(lo);
    y = __uint_as_float(hi);
}
__device__ __forceinline__ unsigned long long fma2(unsigned long long a, unsigned long long b,
                                                   unsigned long long c) {
    unsigned long long d;
    asm("fma.rn.f32x2 %0, %1, %2, %3;" : "=l"(d) : "l"(a), "l"(b), "l"(c));
    return d;
}

// ============================================================================
// K1: projection  h = leaky_relu(ego @ Wfull + bfull)
//   TWO threads per node: each computes 32 of the 64 outputs (16 packed f32x2
//   accumulators, ~60 regs vs 108) -> ~2x occupancy on an issue/latency-bound
//   kernel. Paired threads load the same ego float4 (warp broadcast).
// ============================================================================
__global__ __launch_bounds__(256) void proj_kernel(const float* __restrict__ ego,
                                                   const float* __restrict__ W,
                                                   const float* __restrict__ b) {
    __shared__ ulonglong2 sW2[64 * 16];  // [k][j2] : outputs 4*j2..4*j2+3 at k
    __shared__ ulonglong2 sB2[16];

    for (int i = threadIdx.x; i < 64 * 16; i += 256) {
        int k = i >> 4, j2 = i & 15;
        int ch = j2 >> 3;
        int d = (4 * j2) & 31;
        const float4 v = *(const float4*)(W + ch * 64 * 32 + k * 32 + d);
        sW2[i] = make_ulonglong2(pack2(v.x, v.y), pack2(v.z, v.w));
    }
    if (threadIdx.x < 16) {
        int j2 = threadIdx.x;
        int ch = j2 >> 3;
        int d = (4 * j2) & 31;
        const float4 v = *(const float4*)(b + ch * 32 + d);
        sB2[j2] = make_ulonglong2(pack2(v.x, v.y), pack2(v.z, v.w));
    }
    __syncthreads();

    int gid = blockIdx.x * 256 + threadIdx.x;
    if (gid >= 2 * NN) return;
    int n = gid >> 1;
    int half = gid & 1;  // which 32 outputs this thread owns

    unsigned long long acc[16];
#pragma unroll
    for (int j2 = 0; j2 < 8; j2++) {
        ulonglong2 bv = sB2[half * 8 + j2];
        acc[2 * j2] = bv.x;
        acc[2 * j2 + 1] = bv.y;
    }

    const float4* er = (const float4*)(ego + (size_t)n * EMB);
#pragma unroll 4
    for (int kk = 0; kk < 16; kk++) {
        float4 ev = er[kk];
        float es[4] = {ev.x, ev.y, ev.z, ev.w};
#pragma unroll
        for (int t = 0; t < 4; t++) {
            unsigned long long ee = pack2(es[t], es[t]);
            const ulonglong2* wr = sW2 + (kk * 4 + t) * 16 + half * 8;
#pragma unroll
            for (int j2 = 0; j2 < 8; j2++) {
                ulonglong2 wv = wr[j2];
                acc[2 * j2] = fma2(ee, wv.x, acc[2 * j2]);
                acc[2 * j2 + 1] = fma2(ee, wv.y, acc[2 * j2 + 1]);
            }
        }
    }

    float4* outp = (float4*)(g_h + (size_t)n * EMB + half * 32);
#pragma unroll
    for (int j = 0; j < 16; j += 2) {
        float a0, a1, c0, c1;
        unpack2(acc[j], a0, a1);
        unpack2(acc[j + 1], c0, c1);
        outp[j >> 1] = make_float4(leaky(a0), leaky(a1), leaky(c0), leaky(c1));
    }
}

// ============================================================================
// CSR build: count -> 2-level exclusive scan -> scatter cols into row order
// Runs SERIALLY, before proj: the 4MB counter/cursor arrays must stay
// L2-resident for the atomics to be cheap (overlapping with proj's 512MB
// stream evicts them -> DRAM-latency RMWs; measured regression in R10).
// ============================================================================
__global__ __launch_bounds__(256) void count_kernel(const int* __restrict__ row) {
    int i = blockIdx.x * 256 + threadIdx.x;  // over NE/4
    if (i >= NE / 4) return;
    int4 r = ((const int4*)row)[i];
    atomicAdd(&g_cursor[r.x], 1);
    atomicAdd(&g_cursor[r.y], 1);
    atomicAdd(&g_cursor[r.z], 1);
    atomicAdd(&g_cursor[r.w], 1);
}

__global__ __launch_bounds__(1024) void scan1_kernel() {
    __shared__ int s[1024];
    int t = threadIdx.x;
    int i = blockIdx.x * 1024 + t;
    int v = (i < NN) ? g_cursor[i] : 0;
    s[t] = v;
    __syncthreads();
#pragma unroll
    for (int d = 1; d < 1024; d <<= 1) {
        int x = (t >= d) ? s[t - d] : 0;
        __syncthreads();
        s[t] += x;
        __syncthreads();
    }
    if (i < NN) g_off[i] = s[t] - v;  // exclusive within block
    if (t == 1023) g_blocksums[blockIdx.x] = s[1023];
}

__global__ __launch_bounds__(1024) void scan2_kernel() {
    __shared__ int s[1024];
    int t = threadIdx.x;
    int v = (t < NBLK) ? g_blocksums[t] : 0;
    s[t] = v;
    __syncthreads();
#pragma unroll
    for (int d = 1; d < 1024; d <<= 1) {
        int x = (t >= d) ? s[t - d] : 0;
        __syncthreads();
        s[t] += x;
        __syncthreads();
    }
    if (t < NBLK) g_blocksums[t] = s[t] - v;  // exclusive block bases
}

__global__ __launch_bounds__(256) void scan3_kernel() {
    int i = blockIdx.x * 256 + threadIdx.x;
    if (i < NN) {
        int o = g_off[i] + g_blocksums[i >> 10];
        g_off[i] = o;
        g_cursor[i] = o;  // scatter cursors start at row base
    }
    if (i == 0) g_off[NN] = NE;
}

__global__ __launch_bounds__(256) void scatter_kernel(const int* __restrict__ row,
                                                      const int* __restrict__ col) {
    int i = blockIdx.x * 256 + threadIdx.x;  // over NE/4
    if (i >= NE / 4) return;
    int4 r = ((const int4*)row)[i];
    int4 c = ((const int4*)col)[i];
    int p;
    p = atomicAdd(&g_cursor[r.x], 1); g_scol[p] = c.x;
    p = atomicAdd(&g_cursor[r.y], 1); g_scol[p] = c.y;
    p = atomicAdd(&g_cursor[r.z], 1); g_scol[p] = c.z;
    p = atomicAdd(&g_cursor[r.w], 1); g_scol[p] = c.w;
}

// ============================================================================
// K2: per-row reduction. One warp per destination row: load h[row] once,
//   stream h[col] for its edges (depth-2 prefetch to cover the dependent
//   scol->h gather chain), accumulate denom and ex*h_col in registers, single
//   coalesced output write with 1/(den+eps) fused. No output atomics.
//   (Max-subtraction elided: logits bounded << fp32 exp overflow; the EPS
//    shift is <= 1e-10 relative either way.)
// ============================================================================
__global__ __launch_bounds__(256) void row_kernel(float* __restrict__ out) {
    int w = (blockIdx.x * 256 + threadIdx.x) >> 5;  // row id
    if (w >= NN) return;
    int lane = threadIdx.x & 31;
    int beg = g_off[w];
    int end = g_off[w + 1];

    const float2* hb = (const float2*)g_h;
    float2 a = hb[w * 32 + lane];  // lanes 0-15: ch0 dims, 16-31: ch1 dims
    float ax = 0.0f, ay = 0.0f, den = 0.0f;

    if (beg < end) {
        int c0 = __ldg(g_scol + beg);
        float2 m0 = hb[c0 * 32 + lane];
        float2 m1 = make_float2(0.f, 0.f);
        if (beg + 1 < end) {
            int c1 = __ldg(g_scol + beg + 1);
            m1 = hb[c1 * 32 + lane];
        }
        for (int e = beg; e < end; e++) {
            float2 m = m0;
            m0 = m1;
            if (e + 2 < end) {  // prefetch 2 ahead
                int c2 = __ldg(g_scol + e + 2);
                m1 = hb[c2 * 32 + lane];
            }
            float p = a.x * m.x + a.y * m.y;
            // reduce within each 16-lane half (one channel per half)
            p += __shfl_xor_sync(0xffffffffu, p, 1);
            p += __shfl_xor_sync(0xffffffffu, p, 2);
            p += __shfl_xor_sync(0xffffffffu, p, 4);
            p += __shfl_xor_sync(0xffffffffu, p, 8);
            float ex = __expf(leaky(p));
            den += ex;
            ax = fmaf(ex, m.x, ax);
            ay = fmaf(ex, m.y, ay);
        }
    }
    float s = 1.0f / (den + 1e-10f);  // zero-degree rows: acc=0 -> out=0
    ((float2*)out)[w * 32 + lane] = make_float2(ax * s, ay * s);
}

extern "C" void kernel_launch(void* const* d_in, const int* in_sizes, int n_in,
                              void* d_out, int out_size) {
    const float* ego = (const float*)d_in[0];  // [NN, 64]
    const float* W = (const float*)d_in[1];    // [2, 64, 32]
    const float* b = (const float*)d_in[2];    // [2, 1, 32]
    const int* row = (const int*)d_in[3];      // [NE]
    const int* col = (const int*)d_in[4];      // [NE]
    float* out = (float*)d_out;                // [NN, 64]

    void* cursor_ptr = nullptr;
    cudaGetSymbolAddress(&cursor_ptr, g_cursor);
    cudaMemsetAsync(cursor_ptr, 0, NN * sizeof(int));

    // Strict serial order: atomic kernels keep their counter arrays
    // L2-resident; proj runs after, just before row_kernel (h tail stays warm).
    count_kernel<<<(NE / 4 + 255) / 256, 256>>>(row);
    scan1_kernel<<<NBLK, 1024>>>();
    scan2_kernel<<<1, 1024>>>();
    scan3_kernel<<<(NN + 255) / 256, 256>>>();
    scatter_kernel<<<(NE / 4 + 255) / 256, 256>>>(row, col);

    proj_kernel<<<(2 * NN + 255) / 256, 256>>>(ego, W, b);

    row_kernel<<<(NN * 32 + 255) / 256, 256>>>(out);
}

// round 14
// speedup vs baseline: 1.2032x; 1.2032x over previous
#include <cuda_runtime.h>
#include <cstdint>

#define NN 1000000
#define NE 8000000
#define EMB 64
#define NBLK 977            // ceil(NN/1024)

// Scratch (no cudaMalloc allowed)
__device__ float g_h[(size_t)NN * EMB];   // projected features [NN,64]
__device__ int g_off[NN + 1];             // CSR row offsets (exclusive)
__device__ int g_cursor[NN];              // counts, then scatter cursors
__device__ int g_scol[NE];                // col indices sorted by row
__device__ int g_blocksums[NBLK];

__device__ __forceinline__ float leaky(float x) { return fmaxf(x, 0.01f * x); }

// ---- packed f32x2 helpers (sm_103a) ----
__device__ __forceinline__ unsigned long long pack2(float x, float y) {
    unsigned long long u;
    asm("mov.b64 %0, {%1, %2};" : "=l"(u) : "r"(__float_as_uint(x)), "r"(__float_as_uint(y)));
    return u;
}
__device__ __forceinline__ void unpack2(unsigned long long u, float& x, float& y) {
    unsigned lo, hi;
    asm("mov.b64 {%0, %1}, %2;" : "=r"(lo), "=r"(hi) : "l"(u));
    x = __uint_as_float(lo);
    y = __uint_as_float(hi);
}
__device__ __forceinline__ unsigned long long fma2(unsigned long long a, unsigned long long b,
                                                   unsigned long long c) {
    unsigned long long d;
    asm("fma.rn.f32x2 %0, %1, %2, %3;" : "=l"(d) : "l"(a), "l"(b), "l"(c));
    return d;
}

// ============================================================================
// K1: projection  h = leaky_relu(ego @ Wfull + bfull)
//   ONE thread per node (R9-proven). The kernel is L1-throughput-bound:
//   splitting a node across threads doubles ego LDG wavefronts on the binding
//   resource (measured +190us in R10/R11) — do not re-split.
//   sW2[k][j2] = ulonglong2 of packed f32x2 pairs (LDS.128).
// ============================================================================
__global__ __launch_bounds__(128) void proj_kernel(const float* __restrict__ ego,
                                                   const float* __restrict__ W,
                                                   const float* __restrict__ b) {
    __shared__ ulonglong2 sW2[64 * 16];
    __shared__ ulonglong2 sB2[16];

    for (int i = threadIdx.x; i < 64 * 16; i += 128) {
        int k = i >> 4, j2 = i & 15;
        int ch = j2 >> 3;              // 4*j2 >= 32 ?
        int d = (4 * j2) & 31;
        const float4 v = *(const float4*)(W + ch * 64 * 32 + k * 32 + d);
        sW2[i] = make_ulonglong2(pack2(v.x, v.y), pack2(v.z, v.w));
    }
    if (threadIdx.x < 16) {
        int j2 = threadIdx.x;
        int ch = j2 >> 3;
        int d = (4 * j2) & 31;
        const float4 v = *(const float4*)(b + ch * 32 + d);
        sB2[j2] = make_ulonglong2(pack2(v.x, v.y), pack2(v.z, v.w));
    }
    __syncthreads();

    int n = blockIdx.x * 128 + threadIdx.x;
    if (n >= NN) return;

    unsigned long long acc[32];
#pragma unroll
    for (int j2 = 0; j2 < 16; j2++) {
        ulonglong2 bv = sB2[j2];
        acc[2 * j2] = bv.x;
        acc[2 * j2 + 1] = bv.y;
    }

    const float4* er = (const float4*)(ego + (size_t)n * EMB);
#pragma unroll 4
    for (int kk = 0; kk < 16; kk++) {
        float4 ev = er[kk];
        float es[4] = {ev.x, ev.y, ev.z, ev.w};
#pragma unroll
        for (int t = 0; t < 4; t++) {
            unsigned long long ee = pack2(es[t], es[t]);
            const ulonglong2* wr = sW2 + (kk * 4 + t) * 16;
#pragma unroll
            for (int j2 = 0; j2 < 16; j2++) {
                ulonglong2 wv = wr[j2];
                acc[2 * j2] = fma2(ee, wv.x, acc[2 * j2]);
                acc[2 * j2 + 1] = fma2(ee, wv.y, acc[2 * j2 + 1]);
            }
        }
    }

    float4* outp = (float4*)(g_h + (size_t)n * EMB);
#pragma unroll
    for (int j = 0; j < 32; j += 2) {
        float a0, a1, c0, c1;
        unpack2(acc[j], a0, a1);
        unpack2(acc[j + 1], c0, c1);
        outp[j >> 1] = make_float4(leaky(a0), leaky(a1), leaky(c0), leaky(c1));
    }
}

// ============================================================================
// CSR build: count -> 2-level exclusive scan -> scatter cols into row order
// count uses red.global (no return): spread-address REDG ~0.854 cyc/lane,
// no 318-cycle result scoreboard wait like atomicAdd-with-return.
// ============================================================================
__global__ __launch_bounds__(256) void count_kernel(const int* __restrict__ row) {
    int i = blockIdx.x * 256 + threadIdx.x;  // over NE/4
    if (i >= NE / 4) return;
    int4 r = ((const int4*)row)[i];
    asm volatile("red.global.add.u32 [%0], 1;" ::"l"(&g_cursor[r.x]) : "memory");
    asm volatile("red.global.add.u32 [%0], 1;" ::"l"(&g_cursor[r.y]) : "memory");
    asm volatile("red.global.add.u32 [%0], 1;" ::"l"(&g_cursor[r.z]) : "memory");
    asm volatile("red.global.add.u32 [%0], 1;" ::"l"(&g_cursor[r.w]) : "memory");
}

__global__ __launch_bounds__(1024) void scan1_kernel() {
    __shared__ int s[1024];
    int t = threadIdx.x;
    int i = blockIdx.x * 1024 + t;
    int v = (i < NN) ? g_cursor[i] : 0;
    s[t] = v;
    __syncthreads();
#pragma unroll
    for (int d = 1; d < 1024; d <<= 1) {
        int x = (t >= d) ? s[t - d] : 0;
        __syncthreads();
        s[t] += x;
        __syncthreads();
    }
    if (i < NN) g_off[i] = s[t] - v;  // exclusive within block
    if (t == 1023) g_blocksums[blockIdx.x] = s[1023];
}

__global__ __launch_bounds__(1024) void scan2_kernel() {
    __shared__ int s[1024];
    int t = threadIdx.x;
    int v = (t < NBLK) ? g_blocksums[t] : 0;
    s[t] = v;
    __syncthreads();
#pragma unroll
    for (int d = 1; d < 1024; d <<= 1) {
        int x = (t >= d) ? s[t - d] : 0;
        __syncthreads();
        s[t] += x;
        __syncthreads();
    }
    if (t < NBLK) g_blocksums[t] = s[t] - v;  // exclusive block bases
}

__global__ __launch_bounds__(256) void scan3_kernel() {
    int i = blockIdx.x * 256 + threadIdx.x;
    if (i < NN) {
        int o = g_off[i] + g_blocksums[i >> 10];
        g_off[i] = o;
        g_cursor[i] = o;  // scatter cursors start at row base
    }
    if (i == 0) g_off[NN] = NE;
}

__global__ __launch_bounds__(256) void scatter_kernel(const int* __restrict__ row,
                                                      const int* __restrict__ col) {
    int i = blockIdx.x * 256 + threadIdx.x;  // over NE/4
    if (i >= NE / 4) return;
    int4 r = ((const int4*)row)[i];
    int4 c = ((const int4*)col)[i];
    int p;
    p = atomicAdd(&g_cursor[r.x], 1); g_scol[p] = c.x;
    p = atomicAdd(&g_cursor[r.y], 1); g_scol[p] = c.y;
    p = atomicAdd(&g_cursor[r.z], 1); g_scol[p] = c.z;
    p = atomicAdd(&g_cursor[r.w], 1); g_scol[p] = c.w;
}

// ============================================================================
// K2: per-row reduction (R9-proven depth-1 prefetch). One warp per row:
//   load h[row] once, stream h[col], accumulate denom + ex*h_col in registers,
//   single coalesced write with 1/(den+eps) fused. No output atomics.
//   (Max-subtraction elided: logits bounded << fp32 exp overflow; the EPS
//    shift is <= 1e-10 relative either way.)
// ============================================================================
__global__ __launch_bounds__(256) void row_kernel(float* __restrict__ out) {
    int w = (blockIdx.x * 256 + threadIdx.x) >> 5;  // row id
    if (w >= NN) return;
    int lane = threadIdx.x & 31;
    int beg = g_off[w];
    int end = g_off[w + 1];

    const float2* hb = (const float2*)g_h;
    float2 a = hb[w * 32 + lane];  // lanes 0-15: ch0 dims, 16-31: ch1 dims
    float ax = 0.0f, ay = 0.0f, den = 0.0f;

    if (beg < end) {
        int c0 = __ldg(g_scol + beg);
        float2 m0 = hb[c0 * 32 + lane];
        for (int e = beg; e < end;) {
            float2 m = m0;
            ++e;
            if (e < end) {  // prefetch next neighbor's features
                int c1 = __ldg(g_scol + e);
                m0 = hb[c1 * 32 + lane];
            }
            float p = a.x * m.x + a.y * m.y;
            // reduce within each 16-lane half (one channel per half)
            p += __shfl_xor_sync(0xffffffffu, p, 1);
            p += __shfl_xor_sync(0xffffffffu, p, 2);
            p += __shfl_xor_sync(0xffffffffu, p, 4);
            p += __shfl_xor_sync(0xffffffffu, p, 8);
            float ex = __expf(leaky(p));
            den += ex;
            ax = fmaf(ex, m.x, ax);
            ay = fmaf(ex, m.y, ay);
        }
    }
    float s = 1.0f / (den + 1e-10f);  // zero-degree rows: acc=0 -> out=0
    ((float2*)out)[w * 32 + lane] = make_float2(ax * s, ay * s);
}

extern "C" void kernel_launch(void* const* d_in, const int* in_sizes, int n_in,
                              void* d_out, int out_size) {
    const float* ego = (const float*)d_in[0];  // [NN, 64]
    const float* W = (const float*)d_in[1];    // [2, 64, 32]
    const float* b = (const float*)d_in[2];    // [2, 1, 32]
    const int* row = (const int*)d_in[3];      // [NE]
    const int* col = (const int*)d_in[4];      // [NE]
    float* out = (float*)d_out;                // [NN, 64]

    void* cursor_ptr = nullptr;
    cudaGetSymbolAddress(&cursor_ptr, g_cursor);
    cudaMemsetAsync(cursor_ptr, 0, NN * sizeof(int));

    count_kernel<<<(NE / 4 + 255) / 256, 256>>>(row);
    scan1_kernel<<<NBLK, 1024>>>();
    scan2_kernel<<<1, 1024>>>();
    scan3_kernel<<<(NN + 255) / 256, 256>>>();
    scatter_kernel<<<(NE / 4 + 255) / 256, 256>>>(row, col);

    proj_kernel<<<(NN + 127) / 128, 128>>>(ego, W, b);

    row_kernel<<<(NN * 32 + 255) / 256, 256>>>(out);
}